// round 7
// baseline (speedup 1.0000x reference)
#include <cuda_runtime.h>
#include <cuda_bf16.h>
#include <cstdint>

#define NMAX 50000
#define EMAX 1600000
#define D 128
#define NG 64

// ---------------- scratch (static device globals; no allocation) ----------------
__device__ float g_aggp[NMAX * D];
__device__ float g_aggn[NMAX * D];
__device__ float g_x1[NMAX * D];
__device__ float g_x2[NMAX * D];
__device__ int   g_srcs[EMAX];
__device__ float g_cs[EMAX];
__device__ int   g_rowptr[NMAX + 1];
__device__ int   g_cnt[NMAX];
__device__ int   g_cursor[NMAX];
__device__ float g_degp[NMAX], g_degn[NMAX];
__device__ float g_dinvp[NMAX], g_dinvn[NMAX];
__device__ float g_dp2[NMAX], g_dn2[NMAX];
__device__ int   g_gptr[NG + 1];
__device__ int   g_nz_ei;      // nonzero odd-word found in edge_index => int32
__device__ int   g_nz_batch;   // nonzero odd-word found in batch      => int32
// W transposed + split-bf16: [mat(= layer*2+sign)][n][k]
__device__ __nv_bfloat16 g_wthi[6 * D * D];
__device__ __nv_bfloat16 g_wtlo[6 * D * D];

// read integer element i from a buffer whose dtype (int32 vs int64) is flagged
__device__ __forceinline__ int idx_at(const void* p, size_t i, int is64) {
    if (is64) return (int)((const long long*)p)[i];
    return ((const int*)p)[i];
}

__device__ __forceinline__ const float* sel_x(int s, const float* xext) {
    return s == 0 ? xext : (s == 1 ? g_x1 : g_x2);
}
__device__ __forceinline__ float* sel_out(int s) {
    return s == 1 ? g_x1 : g_x2;
}

// ---------------- dtype probe ----------------
__global__ void k_detect(const unsigned* __restrict__ ei, int n_ei,
                         const unsigned* __restrict__ batch, int n_batch) {
    int t = blockIdx.x * blockDim.x + threadIdx.x;
    int total = gridDim.x * blockDim.x;
    int f1 = 0, f2 = 0;
    for (int w = 1 + 2 * t; w < n_ei; w += 2 * total) f1 |= (ei[w] != 0u);
    for (int w = 1 + 2 * t; w < n_batch; w += 2 * total) f2 |= (batch[w] != 0u);
    if (f1) atomicOr(&g_nz_ei, 1);
    if (f2) atomicOr(&g_nz_batch, 1);
}

// ---------------- preprocessing ----------------
__global__ void k_init(int n) {
    int i = blockIdx.x * blockDim.x + threadIdx.x;
    if (i < n) {
        g_degp[i] = 1.0f;   // self-loop weight
        g_degn[i] = 1.0f;
        g_cnt[i] = 0;
        g_cursor[i] = 0;
    }
}

__global__ void k_zeroflags() {
    g_nz_ei = 0;
    g_nz_batch = 0;
}

__global__ void k_deg(const void* __restrict__ ei, const float* __restrict__ ew, int e) {
    int i = blockIdx.x * blockDim.x + threadIdx.x;
    if (i >= e) return;
    int is64 = !g_nz_ei;
    int dst = idx_at(ei, (size_t)e + i, is64);
    float w = ew[i];
    atomicAdd(&g_degp[dst], fmaxf(w, 0.0f));
    atomicAdd(&g_degn[dst], fmaxf(-w, 0.0f));
    atomicAdd(&g_cnt[dst], 1);
}

__global__ void k_dinv(int n) {
    int i = blockIdx.x * blockDim.x + threadIdx.x;
    if (i < n) {
        float dp = g_degp[i], dn = g_degn[i];
        g_dinvp[i] = rsqrtf(dp);
        g_dinvn[i] = rsqrtf(dn);
        g_dp2[i] = 1.0f / dp;
        g_dn2[i] = 1.0f / dn;
    }
}

// exclusive scan of g_cnt[0..n) into g_rowptr[0..n]
__global__ void k_scan(int n) {
    __shared__ int sm[1024];
    int t = threadIdx.x;
    int CH = (n + 1023) / 1024;
    int base = t * CH;
    int s = 0;
    for (int i = 0; i < CH; i++) {
        int idx = base + i;
        if (idx < n) s += g_cnt[idx];
    }
    sm[t] = s;
    __syncthreads();
    for (int off = 1; off < 1024; off <<= 1) {
        int v = 0;
        if (t >= off) v = sm[t - off];
        __syncthreads();
        if (t >= off) sm[t] += v;
        __syncthreads();
    }
    int excl = (t == 0) ? 0 : sm[t - 1];
    for (int i = 0; i < CH; i++) {
        int idx = base + i;
        if (idx <= n) {
            g_rowptr[idx] = excl;
            if (idx < n) excl += g_cnt[idx];
        }
    }
}

__global__ void k_scatter(const void* __restrict__ ei, const float* __restrict__ ew, int e) {
    int i = blockIdx.x * blockDim.x + threadIdx.x;
    if (i >= e) return;
    int is64 = !g_nz_ei;
    int src = idx_at(ei, (size_t)i, is64);
    int dst = idx_at(ei, (size_t)e + i, is64);
    float w = ew[i];
    float c;
    if (w >= 0.0f) c = w * g_dinvp[src] * g_dinvp[dst];
    else           c = -((-w) * g_dinvn[src] * g_dinvn[dst]);
    int p = g_rowptr[dst] + atomicAdd(&g_cursor[dst], 1);
    g_srcs[p] = src;
    g_cs[p] = c;
}

// gptr[g] = first index with batch[i] >= g (batch is sorted)
__global__ void k_gptr(const void* __restrict__ batch, int n) {
    int t = threadIdx.x;
    if (t > NG) return;
    int is64 = !g_nz_batch;
    int lo = 0, hi = n;
    while (lo < hi) {
        int mid = (lo + hi) >> 1;
        if (idx_at(batch, (size_t)mid, is64) < t) lo = mid + 1; else hi = mid;
    }
    g_gptr[t] = lo;
}

// W prep: transpose to [n][k] and split into bf16 hi/lo (once per replay)
__global__ void k_prepW(const float* __restrict__ Wp, const float* __restrict__ Wn) {
    int i = blockIdx.x * blockDim.x + threadIdx.x;
    if (i >= 6 * D * D) return;
    int m = i / (D * D);
    int r = i % (D * D);
    int nn = r / D;
    int kk = r % D;
    int l = m >> 1, s = m & 1;
    const float* W = s ? Wn : Wp;
    float w = W[l * D * D + kk * D + nn];
    __nv_bfloat16 h = __float2bfloat16(w);
    float lo = w - __bfloat162float(h);
    g_wthi[(size_t)m * D * D + nn * D + kk] = h;
    g_wtlo[(size_t)m * D * D + nn * D + kk] = __float2bfloat16(lo);
}

// ---------------- layer: sparse aggregation (warp per dst node, CSR) ----------------
__global__ void __launch_bounds__(256) k_agg(int xsel, const float* __restrict__ xext, int n) {
    int warp = (blockIdx.x * blockDim.x + threadIdx.x) >> 5;
    if (warp >= n) return;
    const float* __restrict__ x = sel_x(xsel, xext);
    int lane4 = (threadIdx.x & 31) * 4;
    int beg = g_rowptr[warp], end = g_rowptr[warp + 1];
    float4 ap = make_float4(0.f, 0.f, 0.f, 0.f);
    float4 an = make_float4(0.f, 0.f, 0.f, 0.f);
    int i = beg;
    for (; i + 2 <= end; i += 2) {
        int s0 = __ldg(&g_srcs[i]);
        int s1 = __ldg(&g_srcs[i + 1]);
        float c0 = __ldg(&g_cs[i]);
        float c1 = __ldg(&g_cs[i + 1]);
        float4 v0 = *(const float4*)&x[s0 * D + lane4];
        float4 v1 = *(const float4*)&x[s1 * D + lane4];
        if (c0 >= 0.0f) {
            ap.x += c0 * v0.x; ap.y += c0 * v0.y; ap.z += c0 * v0.z; ap.w += c0 * v0.w;
        } else {
            float m = -c0;
            an.x += m * v0.x; an.y += m * v0.y; an.z += m * v0.z; an.w += m * v0.w;
        }
        if (c1 >= 0.0f) {
            ap.x += c1 * v1.x; ap.y += c1 * v1.y; ap.z += c1 * v1.z; ap.w += c1 * v1.w;
        } else {
            float m = -c1;
            an.x += m * v1.x; an.y += m * v1.y; an.z += m * v1.z; an.w += m * v1.w;
        }
    }
    if (i < end) {
        int s0 = __ldg(&g_srcs[i]);
        float c0 = __ldg(&g_cs[i]);
        float4 v0 = *(const float4*)&x[s0 * D + lane4];
        if (c0 >= 0.0f) {
            ap.x += c0 * v0.x; ap.y += c0 * v0.y; ap.z += c0 * v0.z; ap.w += c0 * v0.w;
        } else {
            float m = -c0;
            an.x += m * v0.x; an.y += m * v0.y; an.z += m * v0.z; an.w += m * v0.w;
        }
    }
    *(float4*)&g_aggp[warp * D + lane4] = ap;
    *(float4*)&g_aggn[warp * D + lane4] = an;
}

// ---------------- tensor-core dual GEMM (split-bf16, 3-term) ----------------
// Per CTA: 64 rows x 128 cols; pos and neg passes accumulate in registers,
// epilogue: x_out = relu(accP + bp) - relu(accN + bn).
#define SA 40   // smem row stride in bf16 elems (conflict-free fragment loads)

__device__ __forceinline__ void mma16816(float* c, const uint32_t* a, uint32_t b0, uint32_t b1) {
    asm volatile(
        "mma.sync.aligned.m16n8k16.row.col.f32.bf16.bf16.f32 "
        "{%0,%1,%2,%3}, {%4,%5,%6,%7}, {%8,%9}, {%0,%1,%2,%3};"
        : "+f"(c[0]), "+f"(c[1]), "+f"(c[2]), "+f"(c[3])
        : "r"(a[0]), "r"(a[1]), "r"(a[2]), "r"(a[3]), "r"(b0), "r"(b1));
}

__device__ __forceinline__ void split2(float a, float b, __nv_bfloat162& hi, __nv_bfloat162& lo) {
    __nv_bfloat16 ha = __float2bfloat16(a);
    __nv_bfloat16 hb = __float2bfloat16(b);
    hi = __nv_bfloat162(ha, hb);
    lo = __nv_bfloat162(__float2bfloat16(a - __bfloat162float(ha)),
                        __float2bfloat16(b - __bfloat162float(hb)));
}

__global__ void __launch_bounds__(256) k_gemm_tc(
    int xsel, const float* __restrict__ xext, int layer,
    const float* __restrict__ bpos, const float* __restrict__ bneg,
    int osel, int n)
{
    __shared__ __nv_bfloat16 Ahi[64 * SA], Alo[64 * SA];
    __shared__ __nv_bfloat16 Bhi[D * SA], Blo[D * SA];

    const float* __restrict__ x = sel_x(xsel, xext);
    float* __restrict__ xout = sel_out(osel);

    int tid = threadIdx.x;
    int w = tid >> 5;
    int lane = tid & 31;
    int g = lane >> 2;       // 0..7
    int tig = lane & 3;      // 0..3
    int row0 = blockIdx.x * 64;
    int mr = (w & 3) * 16;          // warp's m-tile base (0,16,32,48)
    int ntbase = (w >> 2) * 8;      // warp's first n-tile (0 or 8)

    float accP[8][4], accN[8][4];
#pragma unroll
    for (int j = 0; j < 8; j++)
#pragma unroll
        for (int q = 0; q < 4; q++) { accP[j][q] = 0.f; accN[j][q] = 0.f; }

    for (int sign = 0; sign < 2; sign++) {
        const float* __restrict__ agg = sign ? g_aggn : g_aggp;
        const float* __restrict__ d2v = sign ? g_dn2 : g_dp2;
        const __nv_bfloat16* __restrict__ wh = g_wthi + (size_t)(layer * 2 + sign) * D * D;
        const __nv_bfloat16* __restrict__ wl = g_wtlo + (size_t)(layer * 2 + sign) * D * D;
        float (*acc)[4] = sign ? accN : accP;

        for (int c = 0; c < 4; c++) {
            int k0 = c * 32;

            // stage A chunk: 64 rows x 32 k, combined (agg + d2*x), split hi/lo
            for (int i = tid; i < 512; i += 256) {
                int row = i >> 3;
                int k4 = (i & 7) * 4;
                int gr = row0 + row;
                float4 a = make_float4(0.f, 0.f, 0.f, 0.f);
                if (gr < n) {
                    float4 ag = *(const float4*)&agg[gr * D + k0 + k4];
                    float4 xv = *(const float4*)&x[gr * D + k0 + k4];
                    float dd = d2v[gr];
                    a.x = ag.x + dd * xv.x;
                    a.y = ag.y + dd * xv.y;
                    a.z = ag.z + dd * xv.z;
                    a.w = ag.w + dd * xv.w;
                }
                __nv_bfloat162 h0, l0, h1, l1;
                split2(a.x, a.y, h0, l0);
                split2(a.z, a.w, h1, l1);
                *(__nv_bfloat162*)&Ahi[row * SA + k4] = h0;
                *(__nv_bfloat162*)&Ahi[row * SA + k4 + 2] = h1;
                *(__nv_bfloat162*)&Alo[row * SA + k4] = l0;
                *(__nv_bfloat162*)&Alo[row * SA + k4 + 2] = l1;
            }

            // stage B chunk: W^T 128 n-rows x 32 k (already bf16 hi/lo in global)
            for (int i = tid; i < 512; i += 256) {
                int nr = i >> 2;
                int q = i & 3;
                ((uint4*)&Bhi[nr * SA])[q] = ((const uint4*)(wh + nr * D + k0))[q];
                ((uint4*)&Blo[nr * SA])[q] = ((const uint4*)(wl + nr * D + k0))[q];
            }
            __syncthreads();

#pragma unroll
            for (int ks = 0; ks < 2; ks++) {
                int kc = ks * 16;
                uint32_t ah[4], al[4];
                int base0 = (mr + g) * SA + kc + tig * 2;
                int base1 = (mr + g + 8) * SA + kc + tig * 2;
                ah[0] = *(const uint32_t*)&Ahi[base0];
                ah[1] = *(const uint32_t*)&Ahi[base1];
                ah[2] = *(const uint32_t*)&Ahi[base0 + 8];
                ah[3] = *(const uint32_t*)&Ahi[base1 + 8];
                al[0] = *(const uint32_t*)&Alo[base0];
                al[1] = *(const uint32_t*)&Alo[base1];
                al[2] = *(const uint32_t*)&Alo[base0 + 8];
                al[3] = *(const uint32_t*)&Alo[base1 + 8];
#pragma unroll
                for (int j = 0; j < 8; j++) {
                    int nrow = (ntbase + j) * 8 + g;
                    int bbase = nrow * SA + kc + tig * 2;
                    uint32_t bh0 = *(const uint32_t*)&Bhi[bbase];
                    uint32_t bh1 = *(const uint32_t*)&Bhi[bbase + 8];
                    uint32_t bl0 = *(const uint32_t*)&Blo[bbase];
                    uint32_t bl1 = *(const uint32_t*)&Blo[bbase + 8];
                    mma16816(acc[j], ah, bh0, bh1);   // hi * hi
                    mma16816(acc[j], ah, bl0, bl1);   // hi * lo
                    mma16816(acc[j], al, bh0, bh1);   // lo * hi
                }
            }
            __syncthreads();
        }
    }

    // epilogue: bias + relu combine + store
    const float* bp = bpos + layer * D;
    const float* bn = bneg + layer * D;
    int r0 = row0 + mr + g;
    int r1 = r0 + 8;
#pragma unroll
    for (int j = 0; j < 8; j++) {
        int col = (ntbase + j) * 8 + tig * 2;
        float2 bpv = *(const float2*)&bp[col];
        float2 bnv = *(const float2*)&bn[col];
        if (r0 < n) {
            float2 o;
            o.x = fmaxf(accP[j][0] + bpv.x, 0.f) - fmaxf(accN[j][0] + bnv.x, 0.f);
            o.y = fmaxf(accP[j][1] + bpv.y, 0.f) - fmaxf(accN[j][1] + bnv.y, 0.f);
            *(float2*)&xout[r0 * D + col] = o;
        }
        if (r1 < n) {
            float2 o;
            o.x = fmaxf(accP[j][2] + bpv.x, 0.f) - fmaxf(accN[j][2] + bnv.x, 0.f);
            o.y = fmaxf(accP[j][3] + bpv.y, 0.f) - fmaxf(accN[j][3] + bnv.y, 0.f);
            *(float2*)&xout[r1 * D + col] = o;
        }
    }
}

// ---------------- pooling + layernorm ----------------
__global__ void k_pool_ln(int xsel, const float* __restrict__ xext,
                          const float* __restrict__ gamma, const float* __restrict__ beta,
                          float* __restrict__ out)
{
    const float* __restrict__ x = sel_x(xsel, xext);
    int g = blockIdx.x;
    int c = threadIdx.x;   // 0..127
    int b = g_gptr[g], e = g_gptr[g + 1];
    float s = 0.f;
    for (int i = b; i < e; i++) s += x[i * D + c];
    float cnt = fmaxf((float)(e - b), 1.0f);
    float p = s / cnt;

    __shared__ float red1[4], red2[4];
    float v1 = p, v2 = p * p;
#pragma unroll
    for (int off = 16; off > 0; off >>= 1) {
        v1 += __shfl_xor_sync(0xffffffff, v1, off);
        v2 += __shfl_xor_sync(0xffffffff, v2, off);
    }
    int w = c >> 5, l = c & 31;
    if (l == 0) { red1[w] = v1; red2[w] = v2; }
    __syncthreads();
    float s1 = red1[0] + red1[1] + red1[2] + red1[3];
    float s2 = red2[0] + red2[1] + red2[2] + red2[3];
    float mu = s1 * (1.0f / D);
    float var = s2 * (1.0f / D) - mu * mu;
    float inv = rsqrtf(var + 1e-5f);
    out[g * D + c] = (p - mu) * inv * gamma[c] + beta[c];
}

// ---------------- launch ----------------
extern "C" void kernel_launch(void* const* d_in, const int* in_sizes, int n_in,
                              void* d_out, int out_size) {
    const float* x = (const float*)d_in[0];
    const void* ei = d_in[1];
    const float* ew = (const float*)d_in[2];
    const void* batch = d_in[3];
    const float* W_pos = (const float*)d_in[4];
    const float* b_pos = (const float*)d_in[5];
    const float* W_neg = (const float*)d_in[6];
    const float* b_neg = (const float*)d_in[7];
    const float* gamma = (const float*)d_in[8];
    const float* beta = (const float*)d_in[9];

    int N = in_sizes[0] / D;
    int E = in_sizes[1] / 2;
    int NB = in_sizes[3];

    int nb = (N + 255) / 256;
    int eb = (E + 255) / 256;

    k_zeroflags<<<1, 1>>>();
    k_detect<<<32, 256>>>((const unsigned*)ei, 2 * E, (const unsigned*)batch, NB);
    k_init<<<nb, 256>>>(N);
    k_deg<<<eb, 256>>>(ei, ew, E);
    k_dinv<<<nb, 256>>>(N);
    k_scan<<<1, 1024>>>(N);
    k_scatter<<<eb, 256>>>(ei, ew, E);
    k_gptr<<<1, 128>>>(batch, N);
    k_prepW<<<(6 * D * D + 255) / 256, 256>>>(W_pos, W_neg);

    int aggBlocks = (N * 32 + 255) / 256;
    int gemmBlocks = (N + 63) / 64;

    // layer 0: x(ext) -> g_x1
    k_agg<<<aggBlocks, 256>>>(0, x, N);
    k_gemm_tc<<<gemmBlocks, 256>>>(0, x, 0, b_pos, b_neg, 1, N);
    // layer 1: g_x1 -> g_x2
    k_agg<<<aggBlocks, 256>>>(1, x, N);
    k_gemm_tc<<<gemmBlocks, 256>>>(1, x, 1, b_pos, b_neg, 2, N);
    // layer 2: g_x2 -> g_x1
    k_agg<<<aggBlocks, 256>>>(2, x, N);
    k_gemm_tc<<<gemmBlocks, 256>>>(2, x, 2, b_pos, b_neg, 1, N);

    k_pool_ln<<<NG, 128>>>(1, x, gamma, beta, (float*)d_out);
}

// round 8
// speedup vs baseline: 1.3180x; 1.3180x over previous
#include <cuda_runtime.h>
#include <cuda_bf16.h>
#include <cstdint>

#define NMAX 50000
#define EMAX 1600000
#define D 128
#define NG 64

// ---------------- scratch (static device globals; no allocation) ----------------
__device__ float g_aggp[NMAX * D];
__device__ float g_aggn[NMAX * D];
__device__ float g_x1[NMAX * D];
__device__ float g_x2[NMAX * D];
__device__ int   g_srcs[EMAX];
__device__ float g_cs[EMAX];
__device__ int   g_rowptr[NMAX + 1];
__device__ int   g_cnt[NMAX];
__device__ int   g_cursor[NMAX];
__device__ float g_degp[NMAX], g_degn[NMAX];
__device__ float g_dinvp[NMAX], g_dinvn[NMAX];
__device__ float g_dp2[NMAX], g_dn2[NMAX];
__device__ int   g_gptr[NG + 1];
__device__ int   g_nz_ei;
__device__ int   g_nz_batch;
// W transposed + split-bf16: [mat(= layer*2+sign)][n][k]
__device__ __nv_bfloat16 g_wthi[6 * D * D];
__device__ __nv_bfloat16 g_wtlo[6 * D * D];

__device__ __forceinline__ int idx_at(const void* p, size_t i, int is64) {
    if (is64) return (int)((const long long*)p)[i];
    return ((const int*)p)[i];
}

__device__ __forceinline__ const float* sel_x(int s, const float* xext) {
    return s == 0 ? xext : (s == 1 ? g_x1 : g_x2);
}
__device__ __forceinline__ float* sel_out(int s) {
    return s == 1 ? g_x1 : g_x2;
}

// ---------------- dtype probe ----------------
__global__ void k_detect(const unsigned* __restrict__ ei, int n_ei,
                         const unsigned* __restrict__ batch, int n_batch) {
    int t = blockIdx.x * blockDim.x + threadIdx.x;
    int total = gridDim.x * blockDim.x;
    int f1 = 0, f2 = 0;
    for (int w = 1 + 2 * t; w < n_ei; w += 2 * total) f1 |= (ei[w] != 0u);
    for (int w = 1 + 2 * t; w < n_batch; w += 2 * total) f2 |= (batch[w] != 0u);
    if (f1) atomicOr(&g_nz_ei, 1);
    if (f2) atomicOr(&g_nz_batch, 1);
}

// ---------------- preprocessing ----------------
__global__ void k_init(int n) {
    int i = blockIdx.x * blockDim.x + threadIdx.x;
    if (i < n) {
        g_degp[i] = 1.0f;
        g_degn[i] = 1.0f;
        g_cnt[i] = 0;
        g_cursor[i] = 0;
    }
}

__global__ void k_zeroflags() {
    g_nz_ei = 0;
    g_nz_batch = 0;
}

__global__ void k_deg(const void* __restrict__ ei, const float* __restrict__ ew, int e) {
    int i = blockIdx.x * blockDim.x + threadIdx.x;
    if (i >= e) return;
    int is64 = !g_nz_ei;
    int dst = idx_at(ei, (size_t)e + i, is64);
    float w = ew[i];
    atomicAdd(&g_degp[dst], fmaxf(w, 0.0f));
    atomicAdd(&g_degn[dst], fmaxf(-w, 0.0f));
    atomicAdd(&g_cnt[dst], 1);
}

__global__ void k_dinv(int n) {
    int i = blockIdx.x * blockDim.x + threadIdx.x;
    if (i < n) {
        float dp = g_degp[i], dn = g_degn[i];
        g_dinvp[i] = rsqrtf(dp);
        g_dinvn[i] = rsqrtf(dn);
        g_dp2[i] = 1.0f / dp;
        g_dn2[i] = 1.0f / dn;
    }
}

__global__ void k_scan(int n) {
    __shared__ int sm[1024];
    int t = threadIdx.x;
    int CH = (n + 1023) / 1024;
    int base = t * CH;
    int s = 0;
    for (int i = 0; i < CH; i++) {
        int idx = base + i;
        if (idx < n) s += g_cnt[idx];
    }
    sm[t] = s;
    __syncthreads();
    for (int off = 1; off < 1024; off <<= 1) {
        int v = 0;
        if (t >= off) v = sm[t - off];
        __syncthreads();
        if (t >= off) sm[t] += v;
        __syncthreads();
    }
    int excl = (t == 0) ? 0 : sm[t - 1];
    for (int i = 0; i < CH; i++) {
        int idx = base + i;
        if (idx <= n) {
            g_rowptr[idx] = excl;
            if (idx < n) excl += g_cnt[idx];
        }
    }
}

__global__ void k_scatter(const void* __restrict__ ei, const float* __restrict__ ew, int e) {
    int i = blockIdx.x * blockDim.x + threadIdx.x;
    if (i >= e) return;
    int is64 = !g_nz_ei;
    int src = idx_at(ei, (size_t)i, is64);
    int dst = idx_at(ei, (size_t)e + i, is64);
    float w = ew[i];
    float c;
    if (w >= 0.0f) c = w * g_dinvp[src] * g_dinvp[dst];
    else           c = -((-w) * g_dinvn[src] * g_dinvn[dst]);
    int p = g_rowptr[dst] + atomicAdd(&g_cursor[dst], 1);
    g_srcs[p] = src;
    g_cs[p] = c;
}

__global__ void k_gptr(const void* __restrict__ batch, int n) {
    int t = threadIdx.x;
    if (t > NG) return;
    int is64 = !g_nz_batch;
    int lo = 0, hi = n;
    while (lo < hi) {
        int mid = (lo + hi) >> 1;
        if (idx_at(batch, (size_t)mid, is64) < t) lo = mid + 1; else hi = mid;
    }
    g_gptr[t] = lo;
}

// W prep: transpose to [n][k] and split into bf16 hi/lo (once per replay)
__global__ void k_prepW(const float* __restrict__ Wp, const float* __restrict__ Wn) {
    int i = blockIdx.x * blockDim.x + threadIdx.x;
    if (i >= 6 * D * D) return;
    int m = i / (D * D);
    int r = i % (D * D);
    int nn = r / D;
    int kk = r % D;
    int l = m >> 1, s = m & 1;
    const float* W = s ? Wn : Wp;
    float w = W[l * D * D + kk * D + nn];
    __nv_bfloat16 h = __float2bfloat16(w);
    float lo = w - __bfloat162float(h);
    g_wthi[(size_t)m * D * D + nn * D + kk] = h;
    g_wtlo[(size_t)m * D * D + nn * D + kk] = __float2bfloat16(lo);
}

// ---------------- layer: sparse aggregation (warp per dst node, CSR) ----------------
__global__ void __launch_bounds__(256) k_agg(int xsel, const float* __restrict__ xext, int n) {
    int warp = (blockIdx.x * blockDim.x + threadIdx.x) >> 5;
    if (warp >= n) return;
    const float* __restrict__ x = sel_x(xsel, xext);
    int lane4 = (threadIdx.x & 31) * 4;
    int beg = g_rowptr[warp], end = g_rowptr[warp + 1];
    float4 ap = make_float4(0.f, 0.f, 0.f, 0.f);
    float4 an = make_float4(0.f, 0.f, 0.f, 0.f);
    int i = beg;
    for (; i + 2 <= end; i += 2) {
        int s0 = __ldg(&g_srcs[i]);
        int s1 = __ldg(&g_srcs[i + 1]);
        float c0 = __ldg(&g_cs[i]);
        float c1 = __ldg(&g_cs[i + 1]);
        float4 v0 = *(const float4*)&x[s0 * D + lane4];
        float4 v1 = *(const float4*)&x[s1 * D + lane4];
        if (c0 >= 0.0f) {
            ap.x += c0 * v0.x; ap.y += c0 * v0.y; ap.z += c0 * v0.z; ap.w += c0 * v0.w;
        } else {
            float m = -c0;
            an.x += m * v0.x; an.y += m * v0.y; an.z += m * v0.z; an.w += m * v0.w;
        }
        if (c1 >= 0.0f) {
            ap.x += c1 * v1.x; ap.y += c1 * v1.y; ap.z += c1 * v1.z; ap.w += c1 * v1.w;
        } else {
            float m = -c1;
            an.x += m * v1.x; an.y += m * v1.y; an.z += m * v1.z; an.w += m * v1.w;
        }
    }
    if (i < end) {
        int s0 = __ldg(&g_srcs[i]);
        float c0 = __ldg(&g_cs[i]);
        float4 v0 = *(const float4*)&x[s0 * D + lane4];
        if (c0 >= 0.0f) {
            ap.x += c0 * v0.x; ap.y += c0 * v0.y; ap.z += c0 * v0.z; ap.w += c0 * v0.w;
        } else {
            float m = -c0;
            an.x += m * v0.x; an.y += m * v0.y; an.z += m * v0.z; an.w += m * v0.w;
        }
    }
    *(float4*)&g_aggp[warp * D + lane4] = ap;
    *(float4*)&g_aggn[warp * D + lane4] = an;
}

// ---------------- tensor-core dual GEMM (split-bf16, 3-term, interleaved signs) ------
// smem layout (bf16 elems), SA=40 stride:
//   Ahi: [2][64][SA]  @ 0       (sign-major)
//   Alo: [2][64][SA]  @ 5120
//   Bhi: [2][128][SA] @ 10240
//   Blo: [2][128][SA] @ 20480
// total 30720 bf16 = 61440 B (dynamic smem)
#define SA 40
#define OFF_ALO 5120
#define OFF_BHI 10240
#define OFF_BLO 20480
#define SMEM_TC_BYTES (30720 * 2)

__device__ __forceinline__ void mma16816(float (&c)[4], const uint32_t (&a)[4], uint32_t b0, uint32_t b1) {
    asm volatile(
        "mma.sync.aligned.m16n8k16.row.col.f32.bf16.bf16.f32 "
        "{%0,%1,%2,%3}, {%4,%5,%6,%7}, {%8,%9}, {%0,%1,%2,%3};"
        : "+f"(c[0]), "+f"(c[1]), "+f"(c[2]), "+f"(c[3])
        : "r"(a[0]), "r"(a[1]), "r"(a[2]), "r"(a[3]), "r"(b0), "r"(b1));
}

// 3-term split product: hi*hi + hi*lo + lo*hi (lo*lo ~ 2^-18, dropped)
__device__ __forceinline__ void mma_tri(float (&acc)[4],
                                        const uint32_t (&ah)[4], const uint32_t (&al)[4],
                                        uint32_t bh0, uint32_t bh1, uint32_t bl0, uint32_t bl1) {
    mma16816(acc, ah, bh0, bh1);
    mma16816(acc, ah, bl0, bl1);
    mma16816(acc, al, bh0, bh1);
}

__device__ __forceinline__ void split2(float a, float b, __nv_bfloat162& hi, __nv_bfloat162& lo) {
    __nv_bfloat16 ha = __float2bfloat16(a);
    __nv_bfloat16 hb = __float2bfloat16(b);
    hi = __nv_bfloat162(ha, hb);
    lo = __nv_bfloat162(__float2bfloat16(a - __bfloat162float(ha)),
                        __float2bfloat16(b - __bfloat162float(hb)));
}

__global__ void __launch_bounds__(256) k_gemm_tc(
    int xsel, const float* __restrict__ xext, int layer,
    const float* __restrict__ bpos, const float* __restrict__ bneg,
    int osel, int n)
{
    extern __shared__ __nv_bfloat16 sm[];

    const float* __restrict__ x = sel_x(xsel, xext);
    float* __restrict__ xout = sel_out(osel);

    int tid = threadIdx.x;
    int w = tid >> 5;
    int lane = tid & 31;
    int g = lane >> 2;       // 0..7
    int tig = lane & 3;      // 0..3
    int row0 = blockIdx.x * 64;
    int mr = (w & 3) * 16;          // warp's m-tile base (0,16,32,48)
    int ntbase = (w >> 2) * 8;      // warp's first n-tile (0 or 8)

    const __nv_bfloat16* __restrict__ whp = g_wthi + (size_t)(layer * 2) * D * D;
    const __nv_bfloat16* __restrict__ whn = whp + D * D;
    const __nv_bfloat16* __restrict__ wlp = g_wtlo + (size_t)(layer * 2) * D * D;
    const __nv_bfloat16* __restrict__ wln = wlp + D * D;

    float accP[8][4], accN[8][4];
#pragma unroll
    for (int j = 0; j < 8; j++)
#pragma unroll
        for (int q = 0; q < 4; q++) { accP[j][q] = 0.f; accN[j][q] = 0.f; }

    for (int c = 0; c < 4; c++) {
        int k0 = c * 32;

        // stage A chunks for BOTH signs: 2 x 64 rows x 32 k, split hi/lo
        for (int i = tid; i < 1024; i += 256) {
            int sign = i >> 9;
            int rem = i & 511;
            int row = rem >> 3;
            int k4 = (rem & 7) * 4;
            int gr = row0 + row;
            const float* agg = sign ? g_aggn : g_aggp;
            const float* d2v = sign ? g_dn2 : g_dp2;
            float4 a = make_float4(0.f, 0.f, 0.f, 0.f);
            if (gr < n) {
                float4 ag = *(const float4*)&agg[gr * D + k0 + k4];
                float4 xv = *(const float4*)&x[gr * D + k0 + k4];
                float dd = d2v[gr];
                a.x = ag.x + dd * xv.x;
                a.y = ag.y + dd * xv.y;
                a.z = ag.z + dd * xv.z;
                a.w = ag.w + dd * xv.w;
            }
            __nv_bfloat162 h0, l0, h1, l1;
            split2(a.x, a.y, h0, l0);
            split2(a.z, a.w, h1, l1);
            int base = sign * 2560 + row * SA + k4;
            *(__nv_bfloat162*)&sm[base] = h0;
            *(__nv_bfloat162*)&sm[base + 2] = h1;
            *(__nv_bfloat162*)&sm[OFF_ALO + base] = l0;
            *(__nv_bfloat162*)&sm[OFF_ALO + base + 2] = l1;
        }

        // stage B chunks for BOTH signs: 2 x 128 n-rows x 32 k (bf16 hi/lo in global)
        for (int i = tid; i < 1024; i += 256) {
            int sign = i >> 9;
            int rem = i & 511;
            int nr = rem >> 2;
            int q = rem & 3;
            const __nv_bfloat16* wh = sign ? whn : whp;
            const __nv_bfloat16* wl = sign ? wln : wlp;
            int base = sign * 5120 + nr * SA;
            ((uint4*)&sm[OFF_BHI + base])[q] = ((const uint4*)(wh + nr * D + k0))[q];
            ((uint4*)&sm[OFF_BLO + base])[q] = ((const uint4*)(wl + nr * D + k0))[q];
        }
        __syncthreads();

#pragma unroll
        for (int ks = 0; ks < 2; ks++) {
            int kc = ks * 16;
            uint32_t ahp[4], alp[4], ahn[4], aln[4];
            int base0 = (mr + g) * SA + kc + tig * 2;
            int base1 = (mr + g + 8) * SA + kc + tig * 2;
            ahp[0] = *(const uint32_t*)&sm[base0];
            ahp[1] = *(const uint32_t*)&sm[base1];
            ahp[2] = *(const uint32_t*)&sm[base0 + 8];
            ahp[3] = *(const uint32_t*)&sm[base1 + 8];
            alp[0] = *(const uint32_t*)&sm[OFF_ALO + base0];
            alp[1] = *(const uint32_t*)&sm[OFF_ALO + base1];
            alp[2] = *(const uint32_t*)&sm[OFF_ALO + base0 + 8];
            alp[3] = *(const uint32_t*)&sm[OFF_ALO + base1 + 8];
            ahn[0] = *(const uint32_t*)&sm[2560 + base0];
            ahn[1] = *(const uint32_t*)&sm[2560 + base1];
            ahn[2] = *(const uint32_t*)&sm[2560 + base0 + 8];
            ahn[3] = *(const uint32_t*)&sm[2560 + base1 + 8];
            aln[0] = *(const uint32_t*)&sm[OFF_ALO + 2560 + base0];
            aln[1] = *(const uint32_t*)&sm[OFF_ALO + 2560 + base1];
            aln[2] = *(const uint32_t*)&sm[OFF_ALO + 2560 + base0 + 8];
            aln[3] = *(const uint32_t*)&sm[OFF_ALO + 2560 + base1 + 8];
#pragma unroll
            for (int j = 0; j < 8; j++) {
                int nrow = (ntbase + j) * 8 + g;
                int bb = nrow * SA + kc + tig * 2;
                uint32_t bh0 = *(const uint32_t*)&sm[OFF_BHI + bb];
                uint32_t bh1 = *(const uint32_t*)&sm[OFF_BHI + bb + 8];
                uint32_t bl0 = *(const uint32_t*)&sm[OFF_BLO + bb];
                uint32_t bl1 = *(const uint32_t*)&sm[OFF_BLO + bb + 8];
                mma_tri(accP[j], ahp, alp, bh0, bh1, bl0, bl1);
                uint32_t ch0 = *(const uint32_t*)&sm[OFF_BHI + 5120 + bb];
                uint32_t ch1 = *(const uint32_t*)&sm[OFF_BHI + 5120 + bb + 8];
                uint32_t cl0 = *(const uint32_t*)&sm[OFF_BLO + 5120 + bb];
                uint32_t cl1 = *(const uint32_t*)&sm[OFF_BLO + 5120 + bb + 8];
                mma_tri(accN[j], ahn, aln, ch0, ch1, cl0, cl1);
            }
        }
        __syncthreads();
    }

    // epilogue: bias + relu combine + store
    const float* bp = bpos + layer * D;
    const float* bn = bneg + layer * D;
    int r0 = row0 + mr + g;
    int r1 = r0 + 8;
#pragma unroll
    for (int j = 0; j < 8; j++) {
        int col = (ntbase + j) * 8 + tig * 2;
        float2 bpv = *(const float2*)&bp[col];
        float2 bnv = *(const float2*)&bn[col];
        if (r0 < n) {
            float2 o;
            o.x = fmaxf(accP[j][0] + bpv.x, 0.f) - fmaxf(accN[j][0] + bnv.x, 0.f);
            o.y = fmaxf(accP[j][1] + bpv.y, 0.f) - fmaxf(accN[j][1] + bnv.y, 0.f);
            *(float2*)&xout[r0 * D + col] = o;
        }
        if (r1 < n) {
            float2 o;
            o.x = fmaxf(accP[j][2] + bpv.x, 0.f) - fmaxf(accN[j][2] + bnv.x, 0.f);
            o.y = fmaxf(accP[j][3] + bpv.y, 0.f) - fmaxf(accN[j][3] + bnv.y, 0.f);
            *(float2*)&xout[r1 * D + col] = o;
        }
    }
}

// ---------------- pooling + layernorm ----------------
__global__ void k_pool_ln(int xsel, const float* __restrict__ xext,
                          const float* __restrict__ gamma, const float* __restrict__ beta,
                          float* __restrict__ out)
{
    const float* __restrict__ x = sel_x(xsel, xext);
    int g = blockIdx.x;
    int c = threadIdx.x;   // 0..127
    int b = g_gptr[g], e = g_gptr[g + 1];
    float s = 0.f;
    for (int i = b; i < e; i++) s += x[i * D + c];
    float cnt = fmaxf((float)(e - b), 1.0f);
    float p = s / cnt;

    __shared__ float red1[4], red2[4];
    float v1 = p, v2 = p * p;
#pragma unroll
    for (int off = 16; off > 0; off >>= 1) {
        v1 += __shfl_xor_sync(0xffffffff, v1, off);
        v2 += __shfl_xor_sync(0xffffffff, v2, off);
    }
    int w = c >> 5, l = c & 31;
    if (l == 0) { red1[w] = v1; red2[w] = v2; }
    __syncthreads();
    float s1 = red1[0] + red1[1] + red1[2] + red1[3];
    float s2 = red2[0] + red2[1] + red2[2] + red2[3];
    float mu = s1 * (1.0f / D);
    float var = s2 * (1.0f / D) - mu * mu;
    float inv = rsqrtf(var + 1e-5f);
    out[g * D + c] = (p - mu) * inv * gamma[c] + beta[c];
}

// ---------------- launch ----------------
extern "C" void kernel_launch(void* const* d_in, const int* in_sizes, int n_in,
                              void* d_out, int out_size) {
    const float* x = (const float*)d_in[0];
    const void* ei = d_in[1];
    const float* ew = (const float*)d_in[2];
    const void* batch = d_in[3];
    const float* W_pos = (const float*)d_in[4];
    const float* b_pos = (const float*)d_in[5];
    const float* W_neg = (const float*)d_in[6];
    const float* b_neg = (const float*)d_in[7];
    const float* gamma = (const float*)d_in[8];
    const float* beta = (const float*)d_in[9];

    int N = in_sizes[0] / D;
    int E = in_sizes[1] / 2;
    int NB = in_sizes[3];

    int nb = (N + 255) / 256;
    int eb = (E + 255) / 256;

    cudaFuncSetAttribute(k_gemm_tc, cudaFuncAttributeMaxDynamicSharedMemorySize, SMEM_TC_BYTES);

    k_zeroflags<<<1, 1>>>();
    k_detect<<<32, 256>>>((const unsigned*)ei, 2 * E, (const unsigned*)batch, NB);
    k_init<<<nb, 256>>>(N);
    k_deg<<<eb, 256>>>(ei, ew, E);
    k_dinv<<<nb, 256>>>(N);
    k_scan<<<1, 1024>>>(N);
    k_scatter<<<eb, 256>>>(ei, ew, E);
    k_gptr<<<1, 128>>>(batch, N);
    k_prepW<<<(6 * D * D + 255) / 256, 256>>>(W_pos, W_neg);

    int aggBlocks = (N * 32 + 255) / 256;
    int gemmBlocks = (N + 63) / 64;

    // layer 0: x(ext) -> g_x1
    k_agg<<<aggBlocks, 256>>>(0, x, N);
    k_gemm_tc<<<gemmBlocks, 256, SMEM_TC_BYTES>>>(0, x, 0, b_pos, b_neg, 1, N);
    // layer 1: g_x1 -> g_x2
    k_agg<<<aggBlocks, 256>>>(1, x, N);
    k_gemm_tc<<<gemmBlocks, 256, SMEM_TC_BYTES>>>(1, x, 1, b_pos, b_neg, 2, N);
    // layer 2: g_x2 -> g_x1
    k_agg<<<aggBlocks, 256>>>(2, x, N);
    k_gemm_tc<<<gemmBlocks, 256, SMEM_TC_BYTES>>>(2, x, 2, b_pos, b_neg, 1, N);

    k_pool_ln<<<NG, 128>>>(1, x, gamma, beta, (float*)d_out);
}

// round 9
// speedup vs baseline: 1.3287x; 1.0081x over previous
#include <cuda_runtime.h>
#include <cuda_bf16.h>
#include <cuda_fp16.h>
#include <cstdint>

#define NMAX 50000
#define EMAX 1600000
#define D 128
#define NG 64

// ---------------- scratch (static device globals; no allocation) ----------------
__device__ float g_aggp[NMAX * D];
__device__ float g_aggn[NMAX * D];
__device__ float g_x1[NMAX * D];
__device__ float g_x2[NMAX * D];
__device__ __half g_xh[NMAX * D];          // fp16 copy of current layer input (gather operand)
__device__ int   g_srcs[EMAX];
__device__ float g_cs[EMAX];
__device__ int   g_rowptr[NMAX + 1];
__device__ int   g_cnt[NMAX];
__device__ int   g_cursor[NMAX];
__device__ float g_degp[NMAX], g_degn[NMAX];
__device__ float g_dinvp[NMAX], g_dinvn[NMAX];
__device__ float g_dp2[NMAX], g_dn2[NMAX];
__device__ int   g_gptr[NG + 1];
__device__ int   g_nz_ei;
__device__ int   g_nz_batch;
// W transposed + split-bf16: [mat(= layer*2+sign)][n][k]
__device__ __nv_bfloat16 g_wthi[6 * D * D];
__device__ __nv_bfloat16 g_wtlo[6 * D * D];

__device__ __forceinline__ int idx_at(const void* p, size_t i, int is64) {
    if (is64) return (int)((const long long*)p)[i];
    return ((const int*)p)[i];
}

__device__ __forceinline__ const float* sel_x(int s, const float* xext) {
    return s == 0 ? xext : (s == 1 ? g_x1 : g_x2);
}
__device__ __forceinline__ float* sel_out(int s) {
    return s == 1 ? g_x1 : g_x2;
}

// ---------------- dtype probe ----------------
__global__ void k_detect(const unsigned* __restrict__ ei, int n_ei,
                         const unsigned* __restrict__ batch, int n_batch) {
    int t = blockIdx.x * blockDim.x + threadIdx.x;
    int total = gridDim.x * blockDim.x;
    int f1 = 0, f2 = 0;
    for (int w = 1 + 2 * t; w < n_ei; w += 2 * total) f1 |= (ei[w] != 0u);
    for (int w = 1 + 2 * t; w < n_batch; w += 2 * total) f2 |= (batch[w] != 0u);
    if (f1) atomicOr(&g_nz_ei, 1);
    if (f2) atomicOr(&g_nz_batch, 1);
}

// ---------------- preprocessing ----------------
__global__ void k_init(int n) {
    int i = blockIdx.x * blockDim.x + threadIdx.x;
    if (i < n) {
        g_degp[i] = 1.0f;
        g_degn[i] = 1.0f;
        g_cnt[i] = 0;
        g_cursor[i] = 0;
    }
}

__global__ void k_zeroflags() {
    g_nz_ei = 0;
    g_nz_batch = 0;
}

__global__ void k_deg(const void* __restrict__ ei, const float* __restrict__ ew, int e) {
    int i = blockIdx.x * blockDim.x + threadIdx.x;
    if (i >= e) return;
    int is64 = !g_nz_ei;
    int dst = idx_at(ei, (size_t)e + i, is64);
    float w = ew[i];
    if (w >= 0.0f) atomicAdd(&g_degp[dst], w);
    else           atomicAdd(&g_degn[dst], -w);
    atomicAdd(&g_cnt[dst], 1);
}

__global__ void k_dinv(int n) {
    int i = blockIdx.x * blockDim.x + threadIdx.x;
    if (i < n) {
        float dp = g_degp[i], dn = g_degn[i];
        g_dinvp[i] = rsqrtf(dp);
        g_dinvn[i] = rsqrtf(dn);
        g_dp2[i] = 1.0f / dp;
        g_dn2[i] = 1.0f / dn;
    }
}

__global__ void k_scan(int n) {
    __shared__ int sm[1024];
    int t = threadIdx.x;
    int CH = (n + 1023) / 1024;
    int base = t * CH;
    int s = 0;
    for (int i = 0; i < CH; i++) {
        int idx = base + i;
        if (idx < n) s += g_cnt[idx];
    }
    sm[t] = s;
    __syncthreads();
    for (int off = 1; off < 1024; off <<= 1) {
        int v = 0;
        if (t >= off) v = sm[t - off];
        __syncthreads();
        if (t >= off) sm[t] += v;
        __syncthreads();
    }
    int excl = (t == 0) ? 0 : sm[t - 1];
    for (int i = 0; i < CH; i++) {
        int idx = base + i;
        if (idx <= n) {
            g_rowptr[idx] = excl;
            if (idx < n) excl += g_cnt[idx];
        }
    }
}

__global__ void k_scatter(const void* __restrict__ ei, const float* __restrict__ ew, int e) {
    int i = blockIdx.x * blockDim.x + threadIdx.x;
    if (i >= e) return;
    int is64 = !g_nz_ei;
    int src = idx_at(ei, (size_t)i, is64);
    int dst = idx_at(ei, (size_t)e + i, is64);
    float w = ew[i];
    float c;
    if (w >= 0.0f) c = w * g_dinvp[src] * g_dinvp[dst];
    else           c = -((-w) * g_dinvn[src] * g_dinvn[dst]);
    int p = g_rowptr[dst] + atomicAdd(&g_cursor[dst], 1);
    g_srcs[p] = src;
    g_cs[p] = c;
}

__global__ void k_gptr(const void* __restrict__ batch, int n) {
    int t = threadIdx.x;
    if (t > NG) return;
    int is64 = !g_nz_batch;
    int lo = 0, hi = n;
    while (lo < hi) {
        int mid = (lo + hi) >> 1;
        if (idx_at(batch, (size_t)mid, is64) < t) lo = mid + 1; else hi = mid;
    }
    g_gptr[t] = lo;
}

// W prep: transpose to [n][k] and split into bf16 hi/lo (once per replay)
__global__ void k_prepW(const float* __restrict__ Wp, const float* __restrict__ Wn) {
    int i = blockIdx.x * blockDim.x + threadIdx.x;
    if (i >= 6 * D * D) return;
    int m = i / (D * D);
    int r = i % (D * D);
    int nn = r / D;
    int kk = r % D;
    int l = m >> 1, s = m & 1;
    const float* W = s ? Wn : Wp;
    float w = W[l * D * D + kk * D + nn];
    __nv_bfloat16 h = __float2bfloat16(w);
    float lo = w - __bfloat162float(h);
    g_wthi[(size_t)m * D * D + nn * D + kk] = h;
    g_wtlo[(size_t)m * D * D + nn * D + kk] = __float2bfloat16(lo);
}

// convert external fp32 x -> fp16 table (layer 0 gather operand)
__global__ void k_x2h(const float* __restrict__ x, int n) {
    int i = blockIdx.x * blockDim.x + threadIdx.x;   // one float4 -> uint2 per thread
    if (i >= n * 32) return;
    float4 v = ((const float4*)x)[i];
    __half2 h0 = __floats2half2_rn(v.x, v.y);
    __half2 h1 = __floats2half2_rn(v.z, v.w);
    uint2 u;
    u.x = *(unsigned*)&h0;
    u.y = *(unsigned*)&h1;
    ((uint2*)g_xh)[i] = u;
}

// ---------------- layer: sparse aggregation (warp per dst node, fp16 gather) --------
__device__ __forceinline__ void acc_edge(float4& ap, float4& an, uint2 u, float c) {
    __half2 h0 = *(__half2*)&u.x;
    __half2 h1 = *(__half2*)&u.y;
    float2 f0 = __half22float2(h0);
    float2 f1 = __half22float2(h1);
    if (c >= 0.0f) {
        ap.x += c * f0.x; ap.y += c * f0.y; ap.z += c * f1.x; ap.w += c * f1.y;
    } else {
        float m = -c;
        an.x += m * f0.x; an.y += m * f0.y; an.z += m * f1.x; an.w += m * f1.y;
    }
}

__global__ void __launch_bounds__(256) k_agg(int n) {
    int warp = (blockIdx.x * blockDim.x + threadIdx.x) >> 5;
    if (warp >= n) return;
    int lane = threadIdx.x & 31;
    const __half* __restrict__ xh = g_xh;
    int beg = g_rowptr[warp], end = g_rowptr[warp + 1];
    float4 ap = make_float4(0.f, 0.f, 0.f, 0.f);
    float4 an = make_float4(0.f, 0.f, 0.f, 0.f);
    int i = beg;
    for (; i + 4 <= end; i += 4) {
        int s0 = __ldg(&g_srcs[i]);
        int s1 = __ldg(&g_srcs[i + 1]);
        int s2 = __ldg(&g_srcs[i + 2]);
        int s3 = __ldg(&g_srcs[i + 3]);
        float c0 = __ldg(&g_cs[i]);
        float c1 = __ldg(&g_cs[i + 1]);
        float c2 = __ldg(&g_cs[i + 2]);
        float c3 = __ldg(&g_cs[i + 3]);
        uint2 u0 = *(const uint2*)&xh[(size_t)s0 * D + lane * 4];
        uint2 u1 = *(const uint2*)&xh[(size_t)s1 * D + lane * 4];
        uint2 u2 = *(const uint2*)&xh[(size_t)s2 * D + lane * 4];
        uint2 u3 = *(const uint2*)&xh[(size_t)s3 * D + lane * 4];
        acc_edge(ap, an, u0, c0);
        acc_edge(ap, an, u1, c1);
        acc_edge(ap, an, u2, c2);
        acc_edge(ap, an, u3, c3);
    }
    for (; i < end; i++) {
        int s0 = __ldg(&g_srcs[i]);
        float c0 = __ldg(&g_cs[i]);
        uint2 u0 = *(const uint2*)&xh[(size_t)s0 * D + lane * 4];
        acc_edge(ap, an, u0, c0);
    }
    *(float4*)&g_aggp[warp * D + lane * 4] = ap;
    *(float4*)&g_aggn[warp * D + lane * 4] = an;
}

// ---------------- tensor-core dual GEMM (split-bf16, 3-term, interleaved signs) ------
#define SA 40
#define OFF_ALO 5120
#define OFF_BHI 10240
#define OFF_BLO 20480
#define SMEM_TC_BYTES (30720 * 2)

__device__ __forceinline__ void mma16816(float (&c)[4], const uint32_t (&a)[4], uint32_t b0, uint32_t b1) {
    asm volatile(
        "mma.sync.aligned.m16n8k16.row.col.f32.bf16.bf16.f32 "
        "{%0,%1,%2,%3}, {%4,%5,%6,%7}, {%8,%9}, {%0,%1,%2,%3};"
        : "+f"(c[0]), "+f"(c[1]), "+f"(c[2]), "+f"(c[3])
        : "r"(a[0]), "r"(a[1]), "r"(a[2]), "r"(a[3]), "r"(b0), "r"(b1));
}

__device__ __forceinline__ void mma_tri(float (&acc)[4],
                                        const uint32_t (&ah)[4], const uint32_t (&al)[4],
                                        uint32_t bh0, uint32_t bh1, uint32_t bl0, uint32_t bl1) {
    mma16816(acc, ah, bh0, bh1);
    mma16816(acc, ah, bl0, bl1);
    mma16816(acc, al, bh0, bh1);
}

__device__ __forceinline__ void split2(float a, float b, __nv_bfloat162& hi, __nv_bfloat162& lo) {
    __nv_bfloat16 ha = __float2bfloat16(a);
    __nv_bfloat16 hb = __float2bfloat16(b);
    hi = __nv_bfloat162(ha, hb);
    lo = __nv_bfloat162(__float2bfloat16(a - __bfloat162float(ha)),
                        __float2bfloat16(b - __bfloat162float(hb)));
}

__global__ void __launch_bounds__(256) k_gemm_tc(
    int xsel, const float* __restrict__ xext, int layer,
    const float* __restrict__ bpos, const float* __restrict__ bneg,
    int osel, int writeH, int n)
{
    extern __shared__ __nv_bfloat16 sm[];

    const float* __restrict__ x = sel_x(xsel, xext);
    float* __restrict__ xout = sel_out(osel);

    int tid = threadIdx.x;
    int w = tid >> 5;
    int lane = tid & 31;
    int g = lane >> 2;
    int tig = lane & 3;
    int row0 = blockIdx.x * 64;
    int mr = (w & 3) * 16;
    int ntbase = (w >> 2) * 8;

    const __nv_bfloat16* __restrict__ whp = g_wthi + (size_t)(layer * 2) * D * D;
    const __nv_bfloat16* __restrict__ whn = whp + D * D;
    const __nv_bfloat16* __restrict__ wlp = g_wtlo + (size_t)(layer * 2) * D * D;
    const __nv_bfloat16* __restrict__ wln = wlp + D * D;

    float accP[8][4], accN[8][4];
#pragma unroll
    for (int j = 0; j < 8; j++)
#pragma unroll
        for (int q = 0; q < 4; q++) { accP[j][q] = 0.f; accN[j][q] = 0.f; }

    for (int c = 0; c < 4; c++) {
        int k0 = c * 32;

        for (int i = tid; i < 1024; i += 256) {
            int sign = i >> 9;
            int rem = i & 511;
            int row = rem >> 3;
            int k4 = (rem & 7) * 4;
            int gr = row0 + row;
            const float* agg = sign ? g_aggn : g_aggp;
            const float* d2v = sign ? g_dn2 : g_dp2;
            float4 a = make_float4(0.f, 0.f, 0.f, 0.f);
            if (gr < n) {
                float4 ag = *(const float4*)&agg[gr * D + k0 + k4];
                float4 xv = *(const float4*)&x[gr * D + k0 + k4];
                float dd = d2v[gr];
                a.x = ag.x + dd * xv.x;
                a.y = ag.y + dd * xv.y;
                a.z = ag.z + dd * xv.z;
                a.w = ag.w + dd * xv.w;
            }
            __nv_bfloat162 h0, l0, h1, l1;
            split2(a.x, a.y, h0, l0);
            split2(a.z, a.w, h1, l1);
            int base = sign * 2560 + row * SA + k4;
            *(__nv_bfloat162*)&sm[base] = h0;
            *(__nv_bfloat162*)&sm[base + 2] = h1;
            *(__nv_bfloat162*)&sm[OFF_ALO + base] = l0;
            *(__nv_bfloat162*)&sm[OFF_ALO + base + 2] = l1;
        }

        for (int i = tid; i < 1024; i += 256) {
            int sign = i >> 9;
            int rem = i & 511;
            int nr = rem >> 2;
            int q = rem & 3;
            const __nv_bfloat16* wh = sign ? whn : whp;
            const __nv_bfloat16* wl = sign ? wln : wlp;
            int base = sign * 5120 + nr * SA;
            ((uint4*)&sm[OFF_BHI + base])[q] = ((const uint4*)(wh + nr * D + k0))[q];
            ((uint4*)&sm[OFF_BLO + base])[q] = ((const uint4*)(wl + nr * D + k0))[q];
        }
        __syncthreads();

#pragma unroll
        for (int ks = 0; ks < 2; ks++) {
            int kc = ks * 16;
            uint32_t ahp[4], alp[4], ahn[4], aln[4];
            int base0 = (mr + g) * SA + kc + tig * 2;
            int base1 = (mr + g + 8) * SA + kc + tig * 2;
            ahp[0] = *(const uint32_t*)&sm[base0];
            ahp[1] = *(const uint32_t*)&sm[base1];
            ahp[2] = *(const uint32_t*)&sm[base0 + 8];
            ahp[3] = *(const uint32_t*)&sm[base1 + 8];
            alp[0] = *(const uint32_t*)&sm[OFF_ALO + base0];
            alp[1] = *(const uint32_t*)&sm[OFF_ALO + base1];
            alp[2] = *(const uint32_t*)&sm[OFF_ALO + base0 + 8];
            alp[3] = *(const uint32_t*)&sm[OFF_ALO + base1 + 8];
            ahn[0] = *(const uint32_t*)&sm[2560 + base0];
            ahn[1] = *(const uint32_t*)&sm[2560 + base1];
            ahn[2] = *(const uint32_t*)&sm[2560 + base0 + 8];
            ahn[3] = *(const uint32_t*)&sm[2560 + base1 + 8];
            aln[0] = *(const uint32_t*)&sm[OFF_ALO + 2560 + base0];
            aln[1] = *(const uint32_t*)&sm[OFF_ALO + 2560 + base1];
            aln[2] = *(const uint32_t*)&sm[OFF_ALO + 2560 + base0 + 8];
            aln[3] = *(const uint32_t*)&sm[OFF_ALO + 2560 + base1 + 8];
#pragma unroll
            for (int j = 0; j < 8; j++) {
                int nrow = (ntbase + j) * 8 + g;
                int bb = nrow * SA + kc + tig * 2;
                uint32_t bh0 = *(const uint32_t*)&sm[OFF_BHI + bb];
                uint32_t bh1 = *(const uint32_t*)&sm[OFF_BHI + bb + 8];
                uint32_t bl0 = *(const uint32_t*)&sm[OFF_BLO + bb];
                uint32_t bl1 = *(const uint32_t*)&sm[OFF_BLO + bb + 8];
                mma_tri(accP[j], ahp, alp, bh0, bh1, bl0, bl1);
                uint32_t ch0 = *(const uint32_t*)&sm[OFF_BHI + 5120 + bb];
                uint32_t ch1 = *(const uint32_t*)&sm[OFF_BHI + 5120 + bb + 8];
                uint32_t cl0 = *(const uint32_t*)&sm[OFF_BLO + 5120 + bb];
                uint32_t cl1 = *(const uint32_t*)&sm[OFF_BLO + 5120 + bb + 8];
                mma_tri(accN[j], ahn, aln, ch0, ch1, cl0, cl1);
            }
        }
        __syncthreads();
    }

    // epilogue: bias + relu combine + store fp32 (+ fp16 copy for next gather)
    const float* bp = bpos + layer * D;
    const float* bn = bneg + layer * D;
    int r0 = row0 + mr + g;
    int r1 = r0 + 8;
#pragma unroll
    for (int j = 0; j < 8; j++) {
        int col = (ntbase + j) * 8 + tig * 2;
        float2 bpv = *(const float2*)&bp[col];
        float2 bnv = *(const float2*)&bn[col];
        if (r0 < n) {
            float2 o;
            o.x = fmaxf(accP[j][0] + bpv.x, 0.f) - fmaxf(accN[j][0] + bnv.x, 0.f);
            o.y = fmaxf(accP[j][1] + bpv.y, 0.f) - fmaxf(accN[j][1] + bnv.y, 0.f);
            *(float2*)&xout[r0 * D + col] = o;
            if (writeH) {
                __half2 hh = __floats2half2_rn(o.x, o.y);
                *(__half2*)&g_xh[r0 * D + col] = hh;
            }
        }
        if (r1 < n) {
            float2 o;
            o.x = fmaxf(accP[j][2] + bpv.x, 0.f) - fmaxf(accN[j][2] + bnv.x, 0.f);
            o.y = fmaxf(accP[j][3] + bpv.y, 0.f) - fmaxf(accN[j][3] + bnv.y, 0.f);
            *(float2*)&xout[r1 * D + col] = o;
            if (writeH) {
                __half2 hh = __floats2half2_rn(o.x, o.y);
                *(__half2*)&g_xh[r1 * D + col] = hh;
            }
        }
    }
}

// ---------------- pooling + layernorm ----------------
__global__ void k_pool_ln(int xsel, const float* __restrict__ xext,
                          const float* __restrict__ gamma, const float* __restrict__ beta,
                          float* __restrict__ out)
{
    const float* __restrict__ x = sel_x(xsel, xext);
    int g = blockIdx.x;
    int c = threadIdx.x;
    int b = g_gptr[g], e = g_gptr[g + 1];
    float s = 0.f;
    for (int i = b; i < e; i++) s += x[i * D + c];
    float cnt = fmaxf((float)(e - b), 1.0f);
    float p = s / cnt;

    __shared__ float red1[4], red2[4];
    float v1 = p, v2 = p * p;
#pragma unroll
    for (int off = 16; off > 0; off >>= 1) {
        v1 += __shfl_xor_sync(0xffffffff, v1, off);
        v2 += __shfl_xor_sync(0xffffffff, v2, off);
    }
    int w = c >> 5, l = c & 31;
    if (l == 0) { red1[w] = v1; red2[w] = v2; }
    __syncthreads();
    float s1 = red1[0] + red1[1] + red1[2] + red1[3];
    float s2 = red2[0] + red2[1] + red2[2] + red2[3];
    float mu = s1 * (1.0f / D);
    float var = s2 * (1.0f / D) - mu * mu;
    float inv = rsqrtf(var + 1e-5f);
    out[g * D + c] = (p - mu) * inv * gamma[c] + beta[c];
}

// ---------------- launch ----------------
extern "C" void kernel_launch(void* const* d_in, const int* in_sizes, int n_in,
                              void* d_out, int out_size) {
    const float* x = (const float*)d_in[0];
    const void* ei = d_in[1];
    const float* ew = (const float*)d_in[2];
    const void* batch = d_in[3];
    const float* W_pos = (const float*)d_in[4];
    const float* b_pos = (const float*)d_in[5];
    const float* W_neg = (const float*)d_in[6];
    const float* b_neg = (const float*)d_in[7];
    const float* gamma = (const float*)d_in[8];
    const float* beta = (const float*)d_in[9];

    int N = in_sizes[0] / D;
    int E = in_sizes[1] / 2;
    int NB = in_sizes[3];

    int nb = (N + 255) / 256;
    int eb = (E + 255) / 256;

    cudaFuncSetAttribute(k_gemm_tc, cudaFuncAttributeMaxDynamicSharedMemorySize, SMEM_TC_BYTES);

    k_zeroflags<<<1, 1>>>();
    k_detect<<<32, 256>>>((const unsigned*)ei, 2 * E, (const unsigned*)batch, NB);
    k_init<<<nb, 256>>>(N);
    k_x2h<<<(N * 32 + 255) / 256, 256>>>(x, N);
    k_deg<<<eb, 256>>>(ei, ew, E);
    k_dinv<<<nb, 256>>>(N);
    k_scan<<<1, 1024>>>(N);
    k_scatter<<<eb, 256>>>(ei, ew, E);
    k_gptr<<<1, 128>>>(batch, N);
    k_prepW<<<(6 * D * D + 255) / 256, 256>>>(W_pos, W_neg);

    int aggBlocks = (N * 32 + 255) / 256;
    int gemmBlocks = (N + 63) / 64;

    // layer 0: x(ext) -> g_x1 (+fp16)
    k_agg<<<aggBlocks, 256>>>(N);
    k_gemm_tc<<<gemmBlocks, 256, SMEM_TC_BYTES>>>(0, x, 0, b_pos, b_neg, 1, 1, N);
    // layer 1: g_x1 -> g_x2 (+fp16)
    k_agg<<<aggBlocks, 256>>>(N);
    k_gemm_tc<<<gemmBlocks, 256, SMEM_TC_BYTES>>>(1, x, 1, b_pos, b_neg, 2, 1, N);
    // layer 2: g_x2 -> g_x1
    k_agg<<<aggBlocks, 256>>>(N);
    k_gemm_tc<<<gemmBlocks, 256, SMEM_TC_BYTES>>>(2, x, 2, b_pos, b_neg, 1, 0, N);

    k_pool_ln<<<NG, 128>>>(1, x, gamma, beta, (float*)d_out);
}